// round 1
// baseline (speedup 1.0000x reference)
#include <cuda_runtime.h>
#include <cstdint>

#define NN   50000
#define DIN  96
#define DOUT 128
#define NE   800000

// Scratch (device-global: no allocations allowed)
__device__ __align__(16) float g_agg[NN * DIN];
__device__ __align__(16) float g_cnt[NN];

// ---------------------------------------------------------------------------
// Kernel 1: zero the accumulators (must run every replay)
// ---------------------------------------------------------------------------
__global__ void zero_kernel() {
    int stride = gridDim.x * blockDim.x;
    int i = blockIdx.x * blockDim.x + threadIdx.x;
    const int n4 = (NN * DIN) / 4;   // 1,200,000
    const int c4 = NN / 4;           // 12,500
    float4 z = make_float4(0.f, 0.f, 0.f, 0.f);
    for (int j = i; j < n4; j += stride) ((float4*)g_agg)[j] = z;
    for (int j = i; j < c4; j += stride) ((float4*)g_cnt)[j] = z;
}

// ---------------------------------------------------------------------------
// Kernel 2: scatter-mean numerator via TMA bulk reduce (cp.reduce.async.bulk)
// One warp per edge per iteration: 24 lanes stage x[src] (384B) into SMEM,
// lane 0 issues a single bulk .add.f32 into g_agg[dst]. Double-buffered.
// ---------------------------------------------------------------------------
__global__ void scatter_kernel(const float* __restrict__ x,
                               const int* __restrict__ ei) {
    __shared__ __align__(16) float buf[8][2][DIN];
    int warp = threadIdx.x >> 5;
    int lane = threadIdx.x & 31;
    int gw = blockIdx.x * (blockDim.x >> 5) + warp;
    int nw = gridDim.x * (blockDim.x >> 5);

    unsigned sb0 = (unsigned)__cvta_generic_to_shared(&buf[warp][0][0]);
    unsigned sb1 = (unsigned)__cvta_generic_to_shared(&buf[warp][1][0]);

    int parity = 0;
    for (int e = gw; e < NE; e += nw) {
        // before overwriting this buffer, make sure the bulk op issued 2
        // iterations ago has finished READING it
        if (lane == 0)
            asm volatile("cp.async.bulk.wait_group.read 1;" ::: "memory");
        __syncwarp();

        int src = ei[e];
        float* b = buf[warp][parity];
        if (lane < 24) {
            float4 v = ((const float4*)(x + (long)src * DIN))[lane];
            ((float4*)b)[lane] = v;
        }
        __syncwarp();

        if (lane == 0) {
            int dst = ei[NE + e];
            unsigned sb = parity ? sb1 : sb0;
            float* gdst = g_agg + (long)dst * DIN;
            asm volatile("fence.proxy.async.shared::cta;" ::: "memory");
            asm volatile(
                "cp.reduce.async.bulk.global.shared::cta.bulk_group.add.f32 "
                "[%0], [%1], %2;"
                :: "l"(gdst), "r"(sb), "r"(DIN * 4) : "memory");
            asm volatile("cp.async.bulk.commit_group;" ::: "memory");
            atomicAdd(&g_cnt[dst], 1.0f);  // no return value -> RED
        }
        parity ^= 1;
    }
    if (lane == 0)
        asm volatile("cp.async.bulk.wait_group 0;" ::: "memory");
}

// ---------------------------------------------------------------------------
// Kernel 3: out = relu( (agg/cnt) @ Wl^T + bl + x @ Wr^T )
// Packed fp32x2 FFMA (2x fp32 rate), k-pairs packed in 64-bit regs.
// Block: 128 threads = 32 col-threads (2 cols each, covering a 64-col half)
//        x 4 row-groups (8 rows each) over a 32-row tile.
// Weights in SMEM column-major, padded to 100 floats (conflict-free LDS.128).
// ---------------------------------------------------------------------------
__device__ __forceinline__ unsigned long long ffma2_(unsigned long long a,
                                                     unsigned long long b,
                                                     unsigned long long c) {
    unsigned long long d;
    asm("fma.rn.f32x2 %0, %1, %2, %3;" : "=l"(d) : "l"(a), "l"(b), "l"(c));
    return d;
}

#define WPAD 100
#define SM_WL 0
#define SM_WR 6400
#define SM_X  12800
#define SM_A  15872
#define SM_FLOATS 18944   // 75776 bytes

__global__ void __launch_bounds__(128) gemm_kernel(
    const float* __restrict__ x, const float* __restrict__ Wl,
    const float* __restrict__ bl, const float* __restrict__ Wr,
    float* __restrict__ out) {
    extern __shared__ __align__(16) float sm[];
    float* sWl = sm + SM_WL;
    float* sWr = sm + SM_WR;
    float* sx  = sm + SM_X;
    float* sa  = sm + SM_A;

    int tid = threadIdx.x;
    int colbase = (blockIdx.x & 1) * 64;

    // load this block's 64-column half of both weight matrices, col-major padded
    for (int i = tid; i < 64 * DIN; i += 128) {
        int c = i / DIN, k = i - c * DIN;
        sWl[c * WPAD + k] = Wl[(colbase + c) * DIN + k];
        sWr[c * WPAD + k] = Wr[(colbase + c) * DIN + k];
    }

    int ct = tid & 31;
    int rbase = (tid >> 5) * 8;
    int c0 = ct, c1 = ct + 32;
    float b0 = bl[colbase + c0];
    float b1 = bl[colbase + c1];

    const int NT = (NN + 31) / 32;  // 1563
    for (int t = blockIdx.x >> 1; t < NT; t += gridDim.x >> 1) {
        int row0 = t * 32;
        __syncthreads();  // prev tile compute done (also fences weight load on iter 0)
        // tile load: 32 rows x 24 float4 per array
        for (int i = tid; i < 32 * 24; i += 128) {
            int r = i / 24, q = i - r * 24;
            int gr = row0 + r; if (gr >= NN) gr = NN - 1;
            ((float4*)(sx + r * DIN))[q] = ((const float4*)(x + (long)gr * DIN))[q];
            float inv = 1.0f / fmaxf(g_cnt[gr], 1.0f);
            float4 av = ((const float4*)(g_agg + (long)gr * DIN))[q];
            av.x *= inv; av.y *= inv; av.z *= inv; av.w *= inv;
            ((float4*)(sa + r * DIN))[q] = av;
        }
        __syncthreads();

        unsigned long long acc0[8], acc1[8];
        #pragma unroll
        for (int r = 0; r < 8; r++) { acc0[r] = 0ull; acc1[r] = 0ull; }

        #pragma unroll 4
        for (int k = 0; k < DIN; k += 4) {
            ulonglong2 wl0 = *(const ulonglong2*)(sWl + c0 * WPAD + k);
            ulonglong2 wl1 = *(const ulonglong2*)(sWl + c1 * WPAD + k);
            ulonglong2 wr0 = *(const ulonglong2*)(sWr + c0 * WPAD + k);
            ulonglong2 wr1 = *(const ulonglong2*)(sWr + c1 * WPAD + k);
            #pragma unroll
            for (int r = 0; r < 8; r++) {
                ulonglong2 av = *(const ulonglong2*)(sa + (rbase + r) * DIN + k);
                ulonglong2 xv = *(const ulonglong2*)(sx + (rbase + r) * DIN + k);
                acc0[r] = ffma2_(wl0.x, av.x, acc0[r]);
                acc0[r] = ffma2_(wl0.y, av.y, acc0[r]);
                acc0[r] = ffma2_(wr0.x, xv.x, acc0[r]);
                acc0[r] = ffma2_(wr0.y, xv.y, acc0[r]);
                acc1[r] = ffma2_(wl1.x, av.x, acc1[r]);
                acc1[r] = ffma2_(wl1.y, av.y, acc1[r]);
                acc1[r] = ffma2_(wr1.x, xv.x, acc1[r]);
                acc1[r] = ffma2_(wr1.y, xv.y, acc1[r]);
            }
        }

        #pragma unroll
        for (int r = 0; r < 8; r++) {
            int row = row0 + rbase + r;
            if (row < NN) {
                float l0 = __uint_as_float((unsigned)(acc0[r] & 0xffffffffull));
                float h0 = __uint_as_float((unsigned)(acc0[r] >> 32));
                float l1 = __uint_as_float((unsigned)(acc1[r] & 0xffffffffull));
                float h1 = __uint_as_float((unsigned)(acc1[r] >> 32));
                float v0 = l0 + h0 + b0;
                float v1 = l1 + h1 + b1;
                out[(long)row * DOUT + colbase + c0] = fmaxf(v0, 0.f);
                out[(long)row * DOUT + colbase + c1] = fmaxf(v1, 0.f);
            }
        }
    }
}

// ---------------------------------------------------------------------------
extern "C" void kernel_launch(void* const* d_in, const int* in_sizes, int n_in,
                              void* d_out, int out_size) {
    const float* x  = (const float*)d_in[0];
    const int*   ei = (const int*)d_in[1];
    const float* Wl = (const float*)d_in[2];
    const float* bl = (const float*)d_in[3];
    const float* Wr = (const float*)d_in[4];
    float* out = (float*)d_out;

    cudaFuncSetAttribute(gemm_kernel, cudaFuncAttributeMaxDynamicSharedMemorySize,
                         SM_FLOATS * (int)sizeof(float));

    zero_kernel<<<512, 256>>>();
    scatter_kernel<<<592, 256>>>(x, ei);
    gemm_kernel<<<444, 128, SM_FLOATS * sizeof(float)>>>(x, Wl, bl, Wr, out);
}

// round 2
// speedup vs baseline: 1.2364x; 1.2364x over previous
#include <cuda_runtime.h>
#include <cstdint>

#define NN   50000
#define DIN  96
#define DOUT 128
#define NE   800000

// Scratch (device-global: no allocations allowed)
__device__ __align__(16) float g_agg[NN * DIN];
__device__ int g_cnt[NN];
__device__ int g_rowstart[NN];
__device__ int g_cursor[NN];
__device__ int g_csr[NE];

// ---------------------------------------------------------------------------
// K1: zero the per-node counters (only state that must be reset per replay;
// cursor/rowstart are overwritten by scan, csr fully overwritten by fill,
// g_agg fully overwritten by agg_kernel)
// ---------------------------------------------------------------------------
__global__ void zero_cnt_kernel() {
    int i = blockIdx.x * blockDim.x + threadIdx.x;
    if (i < NN) g_cnt[i] = 0;
}

// ---------------------------------------------------------------------------
// K2: in-degree counts (REDG, coalesced read of dst array)
// ---------------------------------------------------------------------------
__global__ void count_kernel(const int* __restrict__ ei) {
    int e = blockIdx.x * blockDim.x + threadIdx.x;
    if (e < NE) atomicAdd(&g_cnt[ei[NE + e]], 1);
}

// ---------------------------------------------------------------------------
// K3: exclusive scan of counts -> rowstart (+ cursor copy). Single block.
// ---------------------------------------------------------------------------
__global__ void __launch_bounds__(1024) scan_kernel() {
    __shared__ int wsum[32];
    __shared__ int carry;
    int tid = threadIdx.x, lane = tid & 31, wid = tid >> 5;
    if (tid == 0) carry = 0;
    __syncthreads();
    for (int base = 0; base < NN; base += 1024) {
        int i = base + tid;
        int v = (i < NN) ? g_cnt[i] : 0;
        int s = v;
        #pragma unroll
        for (int o = 1; o < 32; o <<= 1) {
            int t = __shfl_up_sync(0xffffffffu, s, o);
            if (lane >= o) s += t;
        }
        if (lane == 31) wsum[wid] = s;
        __syncthreads();
        if (wid == 0) {
            int ws = wsum[lane];
            #pragma unroll
            for (int o = 1; o < 32; o <<= 1) {
                int t = __shfl_up_sync(0xffffffffu, ws, o);
                if (lane >= o) ws += t;
            }
            wsum[lane] = ws;  // inclusive warp sums
        }
        __syncthreads();
        int warp_off = (wid == 0) ? 0 : wsum[wid - 1];
        int excl = carry + warp_off + s - v;
        if (i < NN) { g_rowstart[i] = excl; g_cursor[i] = excl; }
        __syncthreads();
        if (tid == 0) carry += wsum[31];
        __syncthreads();
    }
}

// ---------------------------------------------------------------------------
// K4: fill CSR adjacency (src ids grouped by dst)
// ---------------------------------------------------------------------------
__global__ void fill_kernel(const int* __restrict__ ei) {
    int e = blockIdx.x * blockDim.x + threadIdx.x;
    if (e < NE) {
        int src = ei[e];
        int dst = ei[NE + e];
        int p = atomicAdd(&g_cursor[dst], 1);
        g_csr[p] = src;
    }
}

// ---------------------------------------------------------------------------
// K5: gather-mean. One warp per destination row; lanes 0..23 each own a
// float4 of the 96-dim row. Each destination row written exactly ONCE.
// Unrolled x2 over neighbors for MLP.
// ---------------------------------------------------------------------------
__global__ void agg_kernel(const float* __restrict__ x) {
    int warp = (blockIdx.x * blockDim.x + threadIdx.x) >> 5;
    int lane = threadIdx.x & 31;
    if (warp >= NN || lane >= 24) return;
    int rs  = g_rowstart[warp];
    int deg = g_cnt[warp];
    float4 a0 = make_float4(0.f, 0.f, 0.f, 0.f);
    float4 a1 = make_float4(0.f, 0.f, 0.f, 0.f);
    int j = 0;
    for (; j + 2 <= deg; j += 2) {
        int s0 = g_csr[rs + j];
        int s1 = g_csr[rs + j + 1];
        float4 v0 = ((const float4*)(x + (long)s0 * DIN))[lane];
        float4 v1 = ((const float4*)(x + (long)s1 * DIN))[lane];
        a0.x += v0.x; a0.y += v0.y; a0.z += v0.z; a0.w += v0.w;
        a1.x += v1.x; a1.y += v1.y; a1.z += v1.z; a1.w += v1.w;
    }
    if (j < deg) {
        int s0 = g_csr[rs + j];
        float4 v0 = ((const float4*)(x + (long)s0 * DIN))[lane];
        a0.x += v0.x; a0.y += v0.y; a0.z += v0.z; a0.w += v0.w;
    }
    float inv = 1.0f / (float)max(deg, 1);
    a0.x = (a0.x + a1.x) * inv;
    a0.y = (a0.y + a1.y) * inv;
    a0.z = (a0.z + a1.z) * inv;
    a0.w = (a0.w + a1.w) * inv;
    ((float4*)(g_agg + (long)warp * DIN))[lane] = a0;
}

// ---------------------------------------------------------------------------
// K6: out = relu( agg @ Wl^T + bl + x @ Wr^T )
// Packed fp32x2 FFMA (2x fp32 rate), k-pairs packed in 64-bit regs.
// ---------------------------------------------------------------------------
__device__ __forceinline__ unsigned long long ffma2_(unsigned long long a,
                                                     unsigned long long b,
                                                     unsigned long long c) {
    unsigned long long d;
    asm("fma.rn.f32x2 %0, %1, %2, %3;" : "=l"(d) : "l"(a), "l"(b), "l"(c));
    return d;
}

#define WPAD 100
#define SM_WL 0
#define SM_WR 6400
#define SM_X  12800
#define SM_A  15872
#define SM_FLOATS 18944   // 75776 bytes

__global__ void __launch_bounds__(128) gemm_kernel(
    const float* __restrict__ x, const float* __restrict__ Wl,
    const float* __restrict__ bl, const float* __restrict__ Wr,
    float* __restrict__ out) {
    extern __shared__ __align__(16) float sm[];
    float* sWl = sm + SM_WL;
    float* sWr = sm + SM_WR;
    float* sx  = sm + SM_X;
    float* sa  = sm + SM_A;

    int tid = threadIdx.x;
    int colbase = (blockIdx.x & 1) * 64;

    // load this block's 64-column half of both weight matrices, col-major padded
    for (int i = tid; i < 64 * DIN; i += 128) {
        int c = i / DIN, k = i - c * DIN;
        sWl[c * WPAD + k] = Wl[(colbase + c) * DIN + k];
        sWr[c * WPAD + k] = Wr[(colbase + c) * DIN + k];
    }

    int ct = tid & 31;
    int rbase = (tid >> 5) * 8;
    int c0 = ct, c1 = ct + 32;
    float b0 = bl[colbase + c0];
    float b1 = bl[colbase + c1];

    const int NT = (NN + 31) / 32;  // 1563
    for (int t = blockIdx.x >> 1; t < NT; t += gridDim.x >> 1) {
        int row0 = t * 32;
        __syncthreads();  // prev tile compute done (also fences weight load on iter 0)
        // tile load: 32 rows x 24 float4 per array
        for (int i = tid; i < 32 * 24; i += 128) {
            int r = i / 24, q = i - r * 24;
            int gr = row0 + r; if (gr >= NN) gr = NN - 1;
            ((float4*)(sx + r * DIN))[q] = ((const float4*)(x + (long)gr * DIN))[q];
            ((float4*)(sa + r * DIN))[q] = ((const float4*)(g_agg + (long)gr * DIN))[q];
        }
        __syncthreads();

        unsigned long long acc0[8], acc1[8];
        #pragma unroll
        for (int r = 0; r < 8; r++) { acc0[r] = 0ull; acc1[r] = 0ull; }

        #pragma unroll 4
        for (int k = 0; k < DIN; k += 4) {
            ulonglong2 wl0 = *(const ulonglong2*)(sWl + c0 * WPAD + k);
            ulonglong2 wl1 = *(const ulonglong2*)(sWl + c1 * WPAD + k);
            ulonglong2 wr0 = *(const ulonglong2*)(sWr + c0 * WPAD + k);
            ulonglong2 wr1 = *(const ulonglong2*)(sWr + c1 * WPAD + k);
            #pragma unroll
            for (int r = 0; r < 8; r++) {
                ulonglong2 av = *(const ulonglong2*)(sa + (rbase + r) * DIN + k);
                ulonglong2 xv = *(const ulonglong2*)(sx + (rbase + r) * DIN + k);
                acc0[r] = ffma2_(wl0.x, av.x, acc0[r]);
                acc0[r] = ffma2_(wl0.y, av.y, acc0[r]);
                acc0[r] = ffma2_(wr0.x, xv.x, acc0[r]);
                acc0[r] = ffma2_(wr0.y, xv.y, acc0[r]);
                acc1[r] = ffma2_(wl1.x, av.x, acc1[r]);
                acc1[r] = ffma2_(wl1.y, av.y, acc1[r]);
                acc1[r] = ffma2_(wr1.x, xv.x, acc1[r]);
                acc1[r] = ffma2_(wr1.y, xv.y, acc1[r]);
            }
        }

        #pragma unroll
        for (int r = 0; r < 8; r++) {
            int row = row0 + rbase + r;
            if (row < NN) {
                float l0 = __uint_as_float((unsigned)(acc0[r] & 0xffffffffull));
                float h0 = __uint_as_float((unsigned)(acc0[r] >> 32));
                float l1 = __uint_as_float((unsigned)(acc1[r] & 0xffffffffull));
                float h1 = __uint_as_float((unsigned)(acc1[r] >> 32));
                float v0 = l0 + h0 + b0;
                float v1 = l1 + h1 + b1;
                out[(long)row * DOUT + colbase + c0] = fmaxf(v0, 0.f);
                out[(long)row * DOUT + colbase + c1] = fmaxf(v1, 0.f);
            }
        }
    }
}

// ---------------------------------------------------------------------------
extern "C" void kernel_launch(void* const* d_in, const int* in_sizes, int n_in,
                              void* d_out, int out_size) {
    const float* x  = (const float*)d_in[0];
    const int*   ei = (const int*)d_in[1];
    const float* Wl = (const float*)d_in[2];
    const float* bl = (const float*)d_in[3];
    const float* Wr = (const float*)d_in[4];
    float* out = (float*)d_out;

    cudaFuncSetAttribute(gemm_kernel, cudaFuncAttributeMaxDynamicSharedMemorySize,
                         SM_FLOATS * (int)sizeof(float));

    zero_cnt_kernel<<<(NN + 255) / 256, 256>>>();
    count_kernel<<<(NE + 255) / 256, 256>>>(ei);
    scan_kernel<<<1, 1024>>>();
    fill_kernel<<<(NE + 255) / 256, 256>>>(ei);
    agg_kernel<<<(NN * 32 + 255) / 256, 256>>>(x);
    gemm_kernel<<<444, 128, SM_FLOATS * sizeof(float)>>>(x, Wl, bl, Wr, out);
}

// round 3
// speedup vs baseline: 1.5797x; 1.2777x over previous
#include <cuda_runtime.h>
#include <cstdint>

#define NN   50000
#define DIN  96
#define DOUT 128
#define NE   800000
#define NB   49          // ceil(NN / 1024)

// Scratch (device-global: no allocations allowed)
__device__ __align__(16) float g_agg[NN * DIN];
__device__ int g_cnt[NN];
__device__ int g_rowstart[NN];   // block-local exclusive prefix
__device__ int g_cursor[NN];     // block-local cursor for fill
__device__ int g_bsum[NB];       // per-1024-block totals
__device__ int g_boff[NB];       // exclusive scan of g_bsum
__device__ int g_csr[NE];

// ---------------------------------------------------------------------------
// K1: zero counters
// ---------------------------------------------------------------------------
__global__ void zero_cnt_kernel() {
    int i = blockIdx.x * blockDim.x + threadIdx.x;
    if (i < NN) g_cnt[i] = 0;
}

// ---------------------------------------------------------------------------
// K2: in-degree counts, 4 edges/thread (int4) for atomic MLP
// ---------------------------------------------------------------------------
__global__ void count_kernel(const int* __restrict__ ei) {
    int t = blockIdx.x * blockDim.x + threadIdx.x;
    if (t < NE / 4) {
        int4 d = ((const int4*)(ei + NE))[t];
        atomicAdd(&g_cnt[d.x], 1);
        atomicAdd(&g_cnt[d.y], 1);
        atomicAdd(&g_cnt[d.z], 1);
        atomicAdd(&g_cnt[d.w], 1);
    }
}

// ---------------------------------------------------------------------------
// K3a: per-block (1024-wide) exclusive scan of counts; emit block totals
// ---------------------------------------------------------------------------
__global__ void __launch_bounds__(1024) scanA_kernel() {
    __shared__ int wsum[32];
    int tid = threadIdx.x, lane = tid & 31, wid = tid >> 5;
    int i = blockIdx.x * 1024 + tid;
    int v = (i < NN) ? g_cnt[i] : 0;
    int s = v;
    #pragma unroll
    for (int o = 1; o < 32; o <<= 1) {
        int t = __shfl_up_sync(0xffffffffu, s, o);
        if (lane >= o) s += t;
    }
    if (lane == 31) wsum[wid] = s;
    __syncthreads();
    if (wid == 0) {
        int ws = wsum[lane];
        #pragma unroll
        for (int o = 1; o < 32; o <<= 1) {
            int t = __shfl_up_sync(0xffffffffu, ws, o);
            if (lane >= o) ws += t;
        }
        wsum[lane] = ws;
    }
    __syncthreads();
    int excl = ((wid == 0) ? 0 : wsum[wid - 1]) + s - v;
    if (i < NN) { g_rowstart[i] = excl; g_cursor[i] = excl; }
    if (tid == 0) g_bsum[blockIdx.x] = wsum[31];
}

// ---------------------------------------------------------------------------
// K3b: exclusive scan of the 49 block totals (single warp, 2 elems/lane)
// ---------------------------------------------------------------------------
__global__ void scanB_kernel() {
    int lane = threadIdx.x;
    int v0 = (lane < NB) ? g_bsum[lane] : 0;
    int v1 = (lane + 32 < NB) ? g_bsum[lane + 32] : 0;
    int s0 = v0;
    #pragma unroll
    for (int o = 1; o < 32; o <<= 1) {
        int t = __shfl_up_sync(0xffffffffu, s0, o);
        if (lane >= o) s0 += t;
    }
    int tot0 = __shfl_sync(0xffffffffu, s0, 31);
    int s1 = v1;
    #pragma unroll
    for (int o = 1; o < 32; o <<= 1) {
        int t = __shfl_up_sync(0xffffffffu, s1, o);
        if (lane >= o) s1 += t;
    }
    if (lane < NB) g_boff[lane] = s0 - v0;
    if (lane + 32 < NB) g_boff[lane + 32] = tot0 + s1 - v1;
}

// ---------------------------------------------------------------------------
// K4: fill CSR, 4 edges/thread. Final slot = local cursor + block offset.
// ---------------------------------------------------------------------------
__global__ void fill_kernel(const int* __restrict__ ei) {
    int t = blockIdx.x * blockDim.x + threadIdx.x;
    if (t < NE / 4) {
        int4 s = ((const int4*)ei)[t];
        int4 d = ((const int4*)(ei + NE))[t];
        int p0 = atomicAdd(&g_cursor[d.x], 1);
        int p1 = atomicAdd(&g_cursor[d.y], 1);
        int p2 = atomicAdd(&g_cursor[d.z], 1);
        int p3 = atomicAdd(&g_cursor[d.w], 1);
        g_csr[p0 + g_boff[d.x >> 10]] = s.x;
        g_csr[p1 + g_boff[d.y >> 10]] = s.y;
        g_csr[p2 + g_boff[d.z >> 10]] = s.z;
        g_csr[p3 + g_boff[d.w >> 10]] = s.w;
    }
}

// ---------------------------------------------------------------------------
// K5: gather-mean. Warp per row, lanes 0..23 own one float4 each.
// Unrolled x4 over neighbors (8 LDG.128 in flight / warp).
// ---------------------------------------------------------------------------
__global__ void agg_kernel(const float* __restrict__ x) {
    int warp = (blockIdx.x * blockDim.x + threadIdx.x) >> 5;
    int lane = threadIdx.x & 31;
    if (warp >= NN || lane >= 24) return;
    int rs  = g_rowstart[warp] + g_boff[warp >> 10];
    int deg = g_cnt[warp];
    float4 a0 = make_float4(0.f, 0.f, 0.f, 0.f);
    float4 a1 = make_float4(0.f, 0.f, 0.f, 0.f);
    int j = 0;
    for (; j + 4 <= deg; j += 4) {
        int s0 = g_csr[rs + j];
        int s1 = g_csr[rs + j + 1];
        int s2 = g_csr[rs + j + 2];
        int s3 = g_csr[rs + j + 3];
        float4 v0 = ((const float4*)(x + (long)s0 * DIN))[lane];
        float4 v1 = ((const float4*)(x + (long)s1 * DIN))[lane];
        float4 v2 = ((const float4*)(x + (long)s2 * DIN))[lane];
        float4 v3 = ((const float4*)(x + (long)s3 * DIN))[lane];
        a0.x += v0.x; a0.y += v0.y; a0.z += v0.z; a0.w += v0.w;
        a1.x += v1.x; a1.y += v1.y; a1.z += v1.z; a1.w += v1.w;
        a0.x += v2.x; a0.y += v2.y; a0.z += v2.z; a0.w += v2.w;
        a1.x += v3.x; a1.y += v3.y; a1.z += v3.z; a1.w += v3.w;
    }
    for (; j < deg; j++) {
        int s0 = g_csr[rs + j];
        float4 v0 = ((const float4*)(x + (long)s0 * DIN))[lane];
        a0.x += v0.x; a0.y += v0.y; a0.z += v0.z; a0.w += v0.w;
    }
    float inv = 1.0f / (float)max(deg, 1);
    a0.x = (a0.x + a1.x) * inv;
    a0.y = (a0.y + a1.y) * inv;
    a0.z = (a0.z + a1.z) * inv;
    a0.w = (a0.w + a1.w) * inv;
    ((float4*)(g_agg + (long)warp * DIN))[lane] = a0;
}

// ---------------------------------------------------------------------------
// K6: out = relu( agg @ Wl^T + bl + x @ Wr^T )   (packed fp32x2 FFMA)
// ---------------------------------------------------------------------------
__device__ __forceinline__ unsigned long long ffma2_(unsigned long long a,
                                                     unsigned long long b,
                                                     unsigned long long c) {
    unsigned long long d;
    asm("fma.rn.f32x2 %0, %1, %2, %3;" : "=l"(d) : "l"(a), "l"(b), "l"(c));
    return d;
}

#define WPAD 100
#define SM_WL 0
#define SM_WR 6400
#define SM_X  12800
#define SM_A  15872
#define SM_FLOATS 18944   // 75776 bytes

__global__ void __launch_bounds__(128) gemm_kernel(
    const float* __restrict__ x, const float* __restrict__ Wl,
    const float* __restrict__ bl, const float* __restrict__ Wr,
    float* __restrict__ out) {
    extern __shared__ __align__(16) float sm[];
    float* sWl = sm + SM_WL;
    float* sWr = sm + SM_WR;
    float* sx  = sm + SM_X;
    float* sa  = sm + SM_A;

    int tid = threadIdx.x;
    int colbase = (blockIdx.x & 1) * 64;

    for (int i = tid; i < 64 * DIN; i += 128) {
        int c = i / DIN, k = i - c * DIN;
        sWl[c * WPAD + k] = Wl[(colbase + c) * DIN + k];
        sWr[c * WPAD + k] = Wr[(colbase + c) * DIN + k];
    }

    int ct = tid & 31;
    int rbase = (tid >> 5) * 8;
    int c0 = ct, c1 = ct + 32;
    float b0 = bl[colbase + c0];
    float b1 = bl[colbase + c1];

    const int NT = (NN + 31) / 32;  // 1563
    for (int t = blockIdx.x >> 1; t < NT; t += gridDim.x >> 1) {
        int row0 = t * 32;
        __syncthreads();
        for (int i = tid; i < 32 * 24; i += 128) {
            int r = i / 24, q = i - r * 24;
            int gr = row0 + r; if (gr >= NN) gr = NN - 1;
            ((float4*)(sx + r * DIN))[q] = ((const float4*)(x + (long)gr * DIN))[q];
            ((float4*)(sa + r * DIN))[q] = ((const float4*)(g_agg + (long)gr * DIN))[q];
        }
        __syncthreads();

        unsigned long long acc0[8], acc1[8];
        #pragma unroll
        for (int r = 0; r < 8; r++) { acc0[r] = 0ull; acc1[r] = 0ull; }

        #pragma unroll 4
        for (int k = 0; k < DIN; k += 4) {
            ulonglong2 wl0 = *(const ulonglong2*)(sWl + c0 * WPAD + k);
            ulonglong2 wl1 = *(const ulonglong2*)(sWl + c1 * WPAD + k);
            ulonglong2 wr0 = *(const ulonglong2*)(sWr + c0 * WPAD + k);
            ulonglong2 wr1 = *(const ulonglong2*)(sWr + c1 * WPAD + k);
            #pragma unroll
            for (int r = 0; r < 8; r++) {
                ulonglong2 av = *(const ulonglong2*)(sa + (rbase + r) * DIN + k);
                ulonglong2 xv = *(const ulonglong2*)(sx + (rbase + r) * DIN + k);
                acc0[r] = ffma2_(wl0.x, av.x, acc0[r]);
                acc0[r] = ffma2_(wl0.y, av.y, acc0[r]);
                acc0[r] = ffma2_(wr0.x, xv.x, acc0[r]);
                acc0[r] = ffma2_(wr0.y, xv.y, acc0[r]);
                acc1[r] = ffma2_(wl1.x, av.x, acc1[r]);
                acc1[r] = ffma2_(wl1.y, av.y, acc1[r]);
                acc1[r] = ffma2_(wr1.x, xv.x, acc1[r]);
                acc1[r] = ffma2_(wr1.y, xv.y, acc1[r]);
            }
        }

        #pragma unroll
        for (int r = 0; r < 8; r++) {
            int row = row0 + rbase + r;
            if (row < NN) {
                float l0 = __uint_as_float((unsigned)(acc0[r] & 0xffffffffull));
                float h0 = __uint_as_float((unsigned)(acc0[r] >> 32));
                float l1 = __uint_as_float((unsigned)(acc1[r] & 0xffffffffull));
                float h1 = __uint_as_float((unsigned)(acc1[r] >> 32));
                float v0 = l0 + h0 + b0;
                float v1 = l1 + h1 + b1;
                out[(long)row * DOUT + colbase + c0] = fmaxf(v0, 0.f);
                out[(long)row * DOUT + colbase + c1] = fmaxf(v1, 0.f);
            }
        }
    }
}

// ---------------------------------------------------------------------------
extern "C" void kernel_launch(void* const* d_in, const int* in_sizes, int n_in,
                              void* d_out, int out_size) {
    const float* x  = (const float*)d_in[0];
    const int*   ei = (const int*)d_in[1];
    const float* Wl = (const float*)d_in[2];
    const float* bl = (const float*)d_in[3];
    const float* Wr = (const float*)d_in[4];
    float* out = (float*)d_out;

    cudaFuncSetAttribute(gemm_kernel, cudaFuncAttributeMaxDynamicSharedMemorySize,
                         SM_FLOATS * (int)sizeof(float));

    zero_cnt_kernel<<<(NN + 255) / 256, 256>>>();
    count_kernel<<<(NE / 4 + 255) / 256, 256>>>(ei);
    scanA_kernel<<<NB, 1024>>>();
    scanB_kernel<<<1, 32>>>();
    fill_kernel<<<(NE / 4 + 255) / 256, 256>>>(ei);
    agg_kernel<<<(NN * 32 + 255) / 256, 256>>>(x);
    gemm_kernel<<<444, 128, SM_FLOATS * sizeof(float)>>>(x, Wl, bl, Wr, out);
}